// round 15
// baseline (speedup 1.0000x reference)
#include <cuda_runtime.h>
#include <math.h>
#include <cstdint>

#define B_ 8
#define N_ 2048
#define IN_ 512
#define OUT_ 32
#define ALPHA_ 0.2f
#define TI 32
#define TJ 32
#define NCH (N_/TJ)

// Precomputed per-node scalars
__device__ __align__(16) float g_w1[IN_];
__device__ __align__(16) float g_w2[IN_];
__device__ __align__(16) float g_f1[B_*N_];
__device__ __align__(16) float g_f2[B_*N_];
__device__ __align__(16) float g_e1p[B_*N_];
__device__ __align__(16) float g_e1n[B_*N_];
__device__ __align__(16) float g_e2p[B_*N_];
__device__ __align__(16) float g_e2n[B_*N_];

// w1 = W_fc^T a1, w2 = W_fc^T a2   (512 threads, 1 block)
__global__ void prep_w_kernel(const float* __restrict__ Wfc,
                              const float* __restrict__ Wattn) {
    int i = threadIdx.x;
    float s1 = 0.f, s2 = 0.f;
#pragma unroll
    for (int o = 0; o < OUT_; o++) {
        float w = Wfc[o * IN_ + i];
        s1 += Wattn[o] * w;
        s2 += Wattn[OUT_ + o] * w;
    }
    g_w1[i] = s1;
    g_w2[i] = s2;
}

// f1,f2 per (b,n) + their exp / exp(alpha*) factors
__global__ void prep_f_kernel(const float* __restrict__ x) {
    int warp = threadIdx.x >> 5, lane = threadIdx.x & 31;
    int row = blockIdx.x * 8 + warp;  // 0..16383
    const float4* xr = (const float4*)(x + (size_t)row * IN_);
    const float4* w1 = (const float4*)g_w1;
    const float4* w2 = (const float4*)g_w2;
    float s1 = 0.f, s2 = 0.f;
#pragma unroll
    for (int q = 0; q < 4; q++) {
        int idx = lane + q * 32;
        float4 v = xr[idx], a = w1[idx], b = w2[idx];
        s1 += v.x * a.x + v.y * a.y + v.z * a.z + v.w * a.w;
        s2 += v.x * b.x + v.y * b.y + v.z * b.z + v.w * b.w;
    }
#pragma unroll
    for (int off = 16; off > 0; off >>= 1) {
        s1 += __shfl_down_sync(0xffffffffu, s1, off);
        s2 += __shfl_down_sync(0xffffffffu, s2, off);
    }
    if (lane == 0) {
        g_f1[row] = s1; g_f2[row] = s2;
        g_e1p[row] = expf(s1);          g_e1n[row] = expf(ALPHA_ * s1);
        g_e2p[row] = expf(s2);          g_e2n[row] = expf(ALPHA_ * s2);
    }
}

__device__ __forceinline__ void cpa16(uint32_t s, const void* g) {
    asm volatile("cp.async.cg.shared.global [%0], [%1], 16;\n" :: "r"(s), "l"(g));
}
__device__ __forceinline__ void cp_commit() {
    asm volatile("cp.async.commit_group;\n");
}
__device__ __forceinline__ void fma2(unsigned long long& d,
                                     unsigned long long a,
                                     unsigned long long b) {
    asm("fma.rn.f32x2 %0, %1, %2, %0;" : "+l"(d) : "l"(a), "l"(b));
}
__device__ __forceinline__ unsigned long long packf2(float a, float b) {
    unsigned long long d;
    asm("mov.b64 %0, {%1,%2};" : "=l"(d) : "f"(a), "f"(b));
    return d;
}

// shared-memory layout (bytes)
#define SMEM_XS   0
#define SMEM_WS   (2 * TJ * IN_ * 4)          /* 131072 : 2x (32x512) f32 x tiles */
#define SMEM_F2   (SMEM_WS + 1056 * 8)        /* 139520 : ws = [32][33] float2    */
#define SMEM_E2P  (SMEM_F2  + N_ * 4)
#define SMEM_E2N  (SMEM_E2P + N_ * 4)
#define SMEM_ZS   (SMEM_E2N + N_ * 4)
#define SMEM_TOTAL (SMEM_ZS + 128)            /* 164224 */

__global__ void __launch_bounds__(256, 1)
gat_main(const float* __restrict__ x, const int* __restrict__ adj,
         float* __restrict__ out) {
    extern __shared__ char sm[];
    float*  xs   = (float*)(sm + SMEM_XS);
    float2* ws   = (float2*)(sm + SMEM_WS);
    float*  sf2  = (float*)(sm + SMEM_F2);
    float*  se2p = (float*)(sm + SMEM_E2P);
    float*  se2n = (float*)(sm + SMEM_E2N);
    float*  zs   = (float*)(sm + SMEM_ZS);

    int tid = threadIdx.x;
    int b   = blockIdx.x >> 6;
    int i0  = (blockIdx.x & 63) << 5;
    const float* xb   = x   + (size_t)b * N_ * IN_;
    const int*   adjb = adj + (size_t)b * N_ * N_;

    // stage f2 / e2p / e2n for the whole batch row range into smem
    {
        const float4* f2g  = (const float4*)(g_f2  + b * N_);
        const float4* e2pg = (const float4*)(g_e2p + b * N_);
        const float4* e2ng = (const float4*)(g_e2n + b * N_);
        float4* f2s = (float4*)sf2; float4* ps = (float4*)se2p; float4* ns = (float4*)se2n;
#pragma unroll
        for (int u = 0; u < 2; u++) {
            int idx = tid + u * 256;          // 0..511 float4s
            f2s[idx] = f2g[idx];
            ps[idx]  = e2pg[idx];
            ns[idx]  = e2ng[idx];
        }
    }

    // per-thread "w duty": row wi, 4 consecutive j's starting at jq
    int wi = tid >> 3;              // 0..31
    int jq = (tid & 7) << 2;        // 0,4,..,28
    float f1i  = g_f1 [b * N_ + i0 + wi];
    float e1pi = g_e1p[b * N_ + i0 + wi];
    float e1ni = g_e1n[b * N_ + i0 + wi];
    const int* adjrow = adjb + (size_t)(i0 + wi) * N_ + jq;

    unsigned long long acc[8][4];
#pragma unroll
    for (int a = 0; a < 8; a++)
#pragma unroll
        for (int k = 0; k < 4; k++) acc[a][k] = 0ull;
    float zacc = 0.f;

    int r8 = (tid >> 6) << 3;       // row group base: 0,8,16,24
    int cc = tid & 63;              // column group 0..63

    uint32_t xs_s = (uint32_t)__cvta_generic_to_shared(xs);

    // prologue: async-load x chunks 0 and 1, prefetch adj chunk 0
#pragma unroll
    for (int u = 0; u < 16; u++) {
        int idx = tid + u * 256;    // float4 index 0..4095
        cpa16(xs_s + idx * 16, xb + idx * 4);
    }
    cp_commit();
#pragma unroll
    for (int u = 0; u < 16; u++) {
        int idx = tid + u * 256;
        cpa16(xs_s + 65536 + idx * 16, xb + TJ * IN_ + idx * 4);
    }
    cp_commit();

    int4 adjv = *(const int4*)(adjrow);
    __syncthreads();   // staging of sf2/se2p/se2n visible

    for (int c = 0; c < NCH; c++) {
        int cb = c & 1;
        int j0 = c * TJ;
        int4 adjn = make_int4(0, 0, 0, 0);
        if (c + 1 < NCH) adjn = *(const int4*)(adjrow + (size_t)(c + 1) * TJ);

        // ---- compute attention weights for chunk c (one thread per 4 entries) ----
        {
            float4 f2v = *(const float4*)(sf2  + j0 + jq);
            float4 epv = *(const float4*)(se2p + j0 + jq);
            float4 env = *(const float4*)(se2n + j0 + jq);
            int   aa[4] = { adjv.x, adjv.y, adjv.z, adjv.w };
            float fv[4] = { f2v.x, f2v.y, f2v.z, f2v.w };
            float pv[4] = { epv.x, epv.y, epv.z, epv.w };
            float nv[4] = { env.x, env.y, env.z, env.w };
#pragma unroll
            for (int q = 0; q < 4; q++) {
                float s = f1i + fv[q];
                float w = (s > 0.f) ? (e1pi * pv[q]) : (e1ni * nv[q]);
                w *= (float)aa[q];
                zacc += w;
                ws[(jq + q) * 33 + wi] = make_float2(w, w);
            }
        }

        if (c + 1 < NCH) asm volatile("cp.async.wait_group 1;\n");
        else             asm volatile("cp.async.wait_group 0;\n");
        __syncthreads();

        // ---- C[32x512] += W[32x32] * X[32x512], packed f32x2 FMA ----
        const float* xsb = xs + (size_t)cb * TJ * IN_;
#pragma unroll 4
        for (int jj = 0; jj < TJ; jj++) {
            const float* xrow = xsb + jj * IN_ + cc * 4;
            float4 xa = *(const float4*)(xrow);
            float4 xc = *(const float4*)(xrow + 256);
            unsigned long long X0 = packf2(xa.x, xa.y);
            unsigned long long X1 = packf2(xa.z, xa.w);
            unsigned long long X2 = packf2(xc.x, xc.y);
            unsigned long long X3 = packf2(xc.z, xc.w);
            const unsigned long long* wr =
                (const unsigned long long*)(ws + jj * 33 + r8);
#pragma unroll
            for (int ii = 0; ii < 8; ii++) {
                unsigned long long W = wr[ii];   // broadcast within warp
                fma2(acc[ii][0], W, X0);
                fma2(acc[ii][1], W, X1);
                fma2(acc[ii][2], W, X2);
                fma2(acc[ii][3], W, X3);
            }
        }
        __syncthreads();

        // issue x chunk c+2 into the buffer we just finished reading
        if (c + 2 < NCH) {
            const float* xg = xb + (size_t)(c + 2) * TJ * IN_;
            uint32_t sdst = xs_s + cb * 65536;
#pragma unroll
            for (int u = 0; u < 16; u++) {
                int idx = tid + u * 256;
                cpa16(sdst + idx * 16, xg + idx * 4);
            }
            cp_commit();
        }
        adjv = adjn;
    }

    // ---- softmax denominator: reduce partial Z over the 8 threads per row ----
    zacc += __shfl_down_sync(0xffffffffu, zacc, 4, 8);
    zacc += __shfl_down_sync(0xffffffffu, zacc, 2, 8);
    zacc += __shfl_down_sync(0xffffffffu, zacc, 1, 8);
    if ((tid & 7) == 0) zs[wi] = zacc;
    __syncthreads();

    // ---- epilogue: normalize, ELU, store ----
    float* outb = out + ((size_t)b * N_ + i0) * IN_;
#pragma unroll
    for (int ii = 0; ii < 8; ii++) {
        int row = r8 + ii;
        float rz = 1.0f / zs[row];
        float v[8];
#pragma unroll
        for (int k = 0; k < 4; k++) {
            float lo, hi;
            asm("mov.b64 {%0,%1}, %2;" : "=f"(lo), "=f"(hi) : "l"(acc[ii][k]));
            v[2 * k] = lo; v[2 * k + 1] = hi;
        }
#pragma unroll
        for (int k = 0; k < 8; k++) {
            float t = v[k] * rz;
            v[k] = (t > 0.f) ? t : expm1f(t);
        }
        float* orow = outb + (size_t)row * IN_;
        *(float4*)(orow + cc * 4)       = make_float4(v[0], v[1], v[2], v[3]);
        *(float4*)(orow + 256 + cc * 4) = make_float4(v[4], v[5], v[6], v[7]);
    }
}

extern "C" void kernel_launch(void* const* d_in, const int* in_sizes, int n_in,
                              void* d_out, int out_size) {
    const float* x     = (const float*)d_in[0];
    const int*   adj   = (const int*)d_in[1];
    const float* Wfc   = (const float*)d_in[2];
    const float* Wattn = (const float*)d_in[3];
    float* out = (float*)d_out;

    prep_w_kernel<<<1, 512>>>(Wfc, Wattn);
    prep_f_kernel<<<(B_ * N_) / 8, 256>>>(x);

    cudaFuncSetAttribute(gat_main, cudaFuncAttributeMaxDynamicSharedMemorySize,
                         SMEM_TOTAL);
    gat_main<<<B_ * (N_ / TI), 256, SMEM_TOTAL>>>(x, adj, out);
}

// round 16
// speedup vs baseline: 1.0007x; 1.0007x over previous
#include <cuda_runtime.h>
#include <math.h>
#include <cstdint>

#define B_ 8
#define N_ 2048
#define IN_ 512
#define OUT_ 32
#define ALPHA_ 0.2f
#define TI 32
#define TJ 32
#define NCH (N_/TJ)

// Precomputed per-node scalars
__device__ __align__(16) float g_w1[IN_];
__device__ __align__(16) float g_w2[IN_];
__device__ __align__(16) float g_f1[B_*N_];
__device__ __align__(16) float g_f2[B_*N_];
__device__ __align__(16) float g_e1p[B_*N_];
__device__ __align__(16) float g_e1n[B_*N_];
__device__ __align__(16) float g_e2p[B_*N_];
__device__ __align__(16) float g_e2n[B_*N_];

// w1 = W_fc^T a1, w2 = W_fc^T a2   (512 threads, 1 block)
__global__ void prep_w_kernel(const float* __restrict__ Wfc,
                              const float* __restrict__ Wattn) {
    int i = threadIdx.x;
    float s1 = 0.f, s2 = 0.f;
#pragma unroll
    for (int o = 0; o < OUT_; o++) {
        float w = Wfc[o * IN_ + i];
        s1 += Wattn[o] * w;
        s2 += Wattn[OUT_ + o] * w;
    }
    g_w1[i] = s1;
    g_w2[i] = s2;
}

// f1,f2 per (b,n) + their exp / exp(alpha*) factors
__global__ void prep_f_kernel(const float* __restrict__ x) {
    int warp = threadIdx.x >> 5, lane = threadIdx.x & 31;
    int row = blockIdx.x * 8 + warp;  // 0..16383
    const float4* xr = (const float4*)(x + (size_t)row * IN_);
    const float4* w1 = (const float4*)g_w1;
    const float4* w2 = (const float4*)g_w2;
    float s1 = 0.f, s2 = 0.f;
#pragma unroll
    for (int q = 0; q < 4; q++) {
        int idx = lane + q * 32;
        float4 v = xr[idx], a = w1[idx], b = w2[idx];
        s1 += v.x * a.x + v.y * a.y + v.z * a.z + v.w * a.w;
        s2 += v.x * b.x + v.y * b.y + v.z * b.z + v.w * b.w;
    }
#pragma unroll
    for (int off = 16; off > 0; off >>= 1) {
        s1 += __shfl_down_sync(0xffffffffu, s1, off);
        s2 += __shfl_down_sync(0xffffffffu, s2, off);
    }
    if (lane == 0) {
        g_f1[row] = s1; g_f2[row] = s2;
        g_e1p[row] = expf(s1);          g_e1n[row] = expf(ALPHA_ * s1);
        g_e2p[row] = expf(s2);          g_e2n[row] = expf(ALPHA_ * s2);
    }
}

__device__ __forceinline__ void cpa16(uint32_t s, const void* g) {
    asm volatile("cp.async.cg.shared.global [%0], [%1], 16;\n" :: "r"(s), "l"(g));
}
__device__ __forceinline__ void cp_commit() {
    asm volatile("cp.async.commit_group;\n");
}
__device__ __forceinline__ void fma2(unsigned long long& d,
                                     unsigned long long a,
                                     unsigned long long b) {
    asm("fma.rn.f32x2 %0, %1, %2, %0;" : "+l"(d) : "l"(a), "l"(b));
}
__device__ __forceinline__ unsigned long long packf2(float a, float b) {
    unsigned long long d;
    asm("mov.b64 %0, {%1,%2};" : "=l"(d) : "f"(a), "f"(b));
    return d;
}

// shared-memory layout (bytes)
#define SMEM_XS   0
#define SMEM_WS   (2 * TJ * IN_ * 4)          /* 131072 : 2x (32x512) f32 x tiles */
#define SMEM_F2   (SMEM_WS + 1056 * 8)        /* 139520 : ws = [32][33] float2    */
#define SMEM_E2P  (SMEM_F2  + N_ * 4)
#define SMEM_E2N  (SMEM_E2P + N_ * 4)
#define SMEM_ZS   (SMEM_E2N + N_ * 4)
#define SMEM_TOTAL (SMEM_ZS + 128)            /* 164224 */

__global__ void __launch_bounds__(256, 1)
gat_main(const float* __restrict__ x, const int* __restrict__ adj,
         float* __restrict__ out) {
    extern __shared__ char sm[];
    float*  xs   = (float*)(sm + SMEM_XS);
    float2* ws   = (float2*)(sm + SMEM_WS);
    float*  sf2  = (float*)(sm + SMEM_F2);
    float*  se2p = (float*)(sm + SMEM_E2P);
    float*  se2n = (float*)(sm + SMEM_E2N);
    float*  zs   = (float*)(sm + SMEM_ZS);

    int tid = threadIdx.x;
    int b   = blockIdx.x >> 6;
    int i0  = (blockIdx.x & 63) << 5;
    const float* xb   = x   + (size_t)b * N_ * IN_;
    const int*   adjb = adj + (size_t)b * N_ * N_;

    // stage f2 / e2p / e2n for the whole batch row range into smem
    {
        const float4* f2g  = (const float4*)(g_f2  + b * N_);
        const float4* e2pg = (const float4*)(g_e2p + b * N_);
        const float4* e2ng = (const float4*)(g_e2n + b * N_);
        float4* f2s = (float4*)sf2; float4* ps = (float4*)se2p; float4* ns = (float4*)se2n;
#pragma unroll
        for (int u = 0; u < 2; u++) {
            int idx = tid + u * 256;          // 0..511 float4s
            f2s[idx] = f2g[idx];
            ps[idx]  = e2pg[idx];
            ns[idx]  = e2ng[idx];
        }
    }

    // per-thread "w duty": row wi, 4 consecutive j's starting at jq
    int wi = tid >> 3;              // 0..31
    int jq = (tid & 7) << 2;        // 0,4,..,28
    float f1i  = g_f1 [b * N_ + i0 + wi];
    float e1pi = g_e1p[b * N_ + i0 + wi];
    float e1ni = g_e1n[b * N_ + i0 + wi];
    const int* adjrow = adjb + (size_t)(i0 + wi) * N_ + jq;

    unsigned long long acc[8][4];
#pragma unroll
    for (int a = 0; a < 8; a++)
#pragma unroll
        for (int k = 0; k < 4; k++) acc[a][k] = 0ull;
    float zacc = 0.f;

    int r8 = (tid >> 6) << 3;       // row group base: 0,8,16,24
    int cc = tid & 63;              // column group 0..63

    uint32_t xs_s = (uint32_t)__cvta_generic_to_shared(xs);

    // prologue: async-load x chunks 0 and 1, prefetch adj chunk 0
#pragma unroll
    for (int u = 0; u < 16; u++) {
        int idx = tid + u * 256;    // float4 index 0..4095
        cpa16(xs_s + idx * 16, xb + idx * 4);
    }
    cp_commit();
#pragma unroll
    for (int u = 0; u < 16; u++) {
        int idx = tid + u * 256;
        cpa16(xs_s + 65536 + idx * 16, xb + TJ * IN_ + idx * 4);
    }
    cp_commit();

    int4 adjv = *(const int4*)(adjrow);
    __syncthreads();   // staging of sf2/se2p/se2n visible

    for (int c = 0; c < NCH; c++) {
        int cb = c & 1;
        int j0 = c * TJ;
        int4 adjn = make_int4(0, 0, 0, 0);
        if (c + 1 < NCH) adjn = *(const int4*)(adjrow + (size_t)(c + 1) * TJ);

        // ---- compute attention weights for chunk c (one thread per 4 entries) ----
        {
            float4 f2v = *(const float4*)(sf2  + j0 + jq);
            float4 epv = *(const float4*)(se2p + j0 + jq);
            float4 env = *(const float4*)(se2n + j0 + jq);
            int   aa[4] = { adjv.x, adjv.y, adjv.z, adjv.w };
            float fv[4] = { f2v.x, f2v.y, f2v.z, f2v.w };
            float pv[4] = { epv.x, epv.y, epv.z, epv.w };
            float nv[4] = { env.x, env.y, env.z, env.w };
#pragma unroll
            for (int q = 0; q < 4; q++) {
                float s = f1i + fv[q];
                float w = (s > 0.f) ? (e1pi * pv[q]) : (e1ni * nv[q]);
                w *= (float)aa[q];
                zacc += w;
                ws[(jq + q) * 33 + wi] = make_float2(w, w);
            }
        }

        if (c + 1 < NCH) asm volatile("cp.async.wait_group 1;\n");
        else             asm volatile("cp.async.wait_group 0;\n");
        __syncthreads();

        // ---- C[32x512] += W[32x32] * X[32x512], packed f32x2 FMA ----
        const float* xsb = xs + (size_t)cb * TJ * IN_;
#pragma unroll 4
        for (int jj = 0; jj < TJ; jj++) {
            const float* xrow = xsb + jj * IN_ + cc * 4;
            float4 xa = *(const float4*)(xrow);
            float4 xc = *(const float4*)(xrow + 256);
            unsigned long long X0 = packf2(xa.x, xa.y);
            unsigned long long X1 = packf2(xa.z, xa.w);
            unsigned long long X2 = packf2(xc.x, xc.y);
            unsigned long long X3 = packf2(xc.z, xc.w);
            const unsigned long long* wr =
                (const unsigned long long*)(ws + jj * 33 + r8);
#pragma unroll
            for (int ii = 0; ii < 8; ii++) {
                unsigned long long W = wr[ii];   // broadcast within warp
                fma2(acc[ii][0], W, X0);
                fma2(acc[ii][1], W, X1);
                fma2(acc[ii][2], W, X2);
                fma2(acc[ii][3], W, X3);
            }
        }
        __syncthreads();

        // issue x chunk c+2 into the buffer we just finished reading
        if (c + 2 < NCH) {
            const float* xg = xb + (size_t)(c + 2) * TJ * IN_;
            uint32_t sdst = xs_s + cb * 65536;
#pragma unroll
            for (int u = 0; u < 16; u++) {
                int idx = tid + u * 256;
                cpa16(sdst + idx * 16, xg + idx * 4);
            }
            cp_commit();
        }
        adjv = adjn;
    }

    // ---- softmax denominator: reduce partial Z over the 8 threads per row ----
    zacc += __shfl_down_sync(0xffffffffu, zacc, 4, 8);
    zacc += __shfl_down_sync(0xffffffffu, zacc, 2, 8);
    zacc += __shfl_down_sync(0xffffffffu, zacc, 1, 8);
    if ((tid & 7) == 0) zs[wi] = zacc;
    __syncthreads();

    // ---- epilogue: normalize, ELU, store ----
    float* outb = out + ((size_t)b * N_ + i0) * IN_;
#pragma unroll
    for (int ii = 0; ii < 8; ii++) {
        int row = r8 + ii;
        float rz = 1.0f / zs[row];
        float v[8];
#pragma unroll
        for (int k = 0; k < 4; k++) {
            float lo, hi;
            asm("mov.b64 {%0,%1}, %2;" : "=f"(lo), "=f"(hi) : "l"(acc[ii][k]));
            v[2 * k] = lo; v[2 * k + 1] = hi;
        }
#pragma unroll
        for (int k = 0; k < 8; k++) {
            float t = v[k] * rz;
            v[k] = (t > 0.f) ? t : expm1f(t);
        }
        float* orow = outb + (size_t)row * IN_;
        *(float4*)(orow + cc * 4)       = make_float4(v[0], v[1], v[2], v[3]);
        *(float4*)(orow + 256 + cc * 4) = make_float4(v[4], v[5], v[6], v[7]);
    }
}

extern "C" void kernel_launch(void* const* d_in, const int* in_sizes, int n_in,
                              void* d_out, int out_size) {
    const float* x     = (const float*)d_in[0];
    const int*   adj   = (const int*)d_in[1];
    const float* Wfc   = (const float*)d_in[2];
    const float* Wattn = (const float*)d_in[3];
    float* out = (float*)d_out;

    prep_w_kernel<<<1, 512>>>(Wfc, Wattn);
    prep_f_kernel<<<(B_ * N_) / 8, 256>>>(x);

    cudaFuncSetAttribute(gat_main, cudaFuncAttributeMaxDynamicSharedMemorySize,
                         SMEM_TOTAL);
    gat_main<<<B_ * (N_ / TI), 256, SMEM_TOTAL>>>(x, adj, out);
}